// round 5
// baseline (speedup 1.0000x reference)
#include <cuda_runtime.h>
#include <cstdint>

#define Bz    4
#define Cc    64
#define Hh    64
#define Ww    64
#define HW    4096
#define CHW   (Cc*HW)
#define PATCH 9
#define CHUNK 16
#define NCH   (Cc/CHUNK)          // 4
#define SROW  72
#define SROWS 10
#define F2BUF (CHUNK*SROWS*SROW)        // 11520 floats
#define F1BUF (CHUNK*2*Ww)              // 2048 floats
#define SMEM_FLOATS (2*(F2BUF+F1BUF))   // 27136
#define SMEM_BYTES  (SMEM_FLOATS*4)     // 108544
#define NTHR  288

// scratch
__device__ float g_inv1[Bz][HW];
__device__ float g_inv2p[Bz][72][72];   // padded inverse norms of f2 (halo = 1.0)

__device__ __forceinline__ uint32_t smem_u32(const void* p) {
    uint32_t a;
    asm("{ .reg .u64 t; cvta.to.shared.u64 t, %1; cvt.u32.u64 %0, t; }" : "=r"(a) : "l"(p));
    return a;
}
__device__ __forceinline__ void cp_async16(uint32_t dst, const float* src, int sz) {
    asm volatile("cp.async.cg.shared.global [%0], [%1], 16, %2;"
                 :: "r"(dst), "l"(src), "r"(sz) : "memory");
}
__device__ __forceinline__ void cp_commit() {
    asm volatile("cp.async.commit_group;" ::: "memory");
}
template<int N>
__device__ __forceinline__ void cp_wait() {
    asm volatile("cp.async.wait_group %0;" :: "n"(N) : "memory");
}

// ---------------------------------------------------------------------------
// Kernel 1: inverse L2 norms. 32768 threads, MLP=16, shfl-reduce.
// ---------------------------------------------------------------------------
__global__ void invnorm_kernel(const float* __restrict__ f1,
                               const float* __restrict__ f2) {
    int idx  = blockIdx.x * 256 + threadIdx.x;          // 0..32767
    int cg   = idx & 3;
    int quad = (idx >> 2) & 1023;
    int b    = (idx >> 12) & 3;
    int feat = idx >> 14;
    const float* src = (feat ? f2 : f1) + b * CHW + quad * 4 + cg * 16 * HW;

    float4 s = make_float4(0.f, 0.f, 0.f, 0.f);
#pragma unroll
    for (int i = 0; i < 16; ++i) {
        float4 v = __ldg((const float4*)(src + i * HW));
        s.x += v.x * v.x; s.y += v.y * v.y; s.z += v.z * v.z; s.w += v.w * v.w;
    }
#pragma unroll
    for (int m = 1; m <= 2; m <<= 1) {
        s.x += __shfl_xor_sync(0xffffffffu, s.x, m);
        s.y += __shfl_xor_sync(0xffffffffu, s.y, m);
        s.z += __shfl_xor_sync(0xffffffffu, s.z, m);
        s.w += __shfl_xor_sync(0xffffffffu, s.w, m);
    }
    if (cg == 0) {
        float4 r;
        r.x = rsqrtf(s.x + 1e-6f); r.y = rsqrtf(s.y + 1e-6f);
        r.z = rsqrtf(s.z + 1e-6f); r.w = rsqrtf(s.w + 1e-6f);
        int y = quad >> 4, x = (quad & 15) << 2;
        if (feat == 0) {
            *(float4*)&g_inv1[b][quad * 4] = r;
        } else {
            *(float4*)&g_inv2p[b][y + 4][x + 4] = r;
        }
    }
    if (idx < Bz * 72 * 72) {
        int bb = idx / 5184;
        int rc = idx - bb * 5184;
        int r  = rc / 72, cc = rc - r * 72;
        if (r < 4 || r >= 68 || cc < 4 || cc >= 68)
            g_inv2p[bb][r][cc] = 1.0f;
    }
}

// ---------------------------------------------------------------------------
// Kernel 2: correlation + relu, dx-split.
//   grid = B*(H/2)*2 = 256 CTAs, 288 threads (9 warps = 9 dy values).
//   bx: [b:2][yp:5][half:1]. half 0 -> dx 0..4, half 1 -> dx 5..8.
//   Outputs disjoint per half; no combine pass. 2 CTAs/SM -> 18 warps/SM.
// ---------------------------------------------------------------------------
template<int DX0, int NDX>
__device__ __forceinline__ void corr_impl(float* smem,
                                          const float* __restrict__ f1,
                                          const float* __restrict__ f2,
                                          float* __restrict__ out) {
    constexpr int VOFF = (DX0 == 0) ? 0 : 4;   // v/e window start offset

    float* s_f2 = smem;
    float* s_f1 = smem + 2 * F2BUF;
    const uint32_t s2_base = smem_u32(s_f2);
    const uint32_t s1_base = smem_u32(s_f1);

    const int b    = blockIdx.x >> 6;
    const int y0   = ((blockIdx.x >> 1) & 31) * 2;
    const int tid  = threadIdx.x;
    const int dy   = tid >> 5;                 // warp = dy (0..8)
    const int lane = tid & 31;
    const int ty   = lane >> 4;
    const int x0   = (lane & 15) << 2;
    const int y    = y0 + ty;

    const float* f2b = f2 + b * CHW;
    const float* f1b = f1 + b * CHW + y0 * Ww;

    auto stage = [&](int c0, int sel) {
        uint32_t d2 = s2_base + sel * (F2BUF * 4);
#pragma unroll
        for (int it = 0; it < 10; ++it) {
            int i   = it * NTHR + tid;
            int c   = i / 180;
            int rem = i - c * 180;
            int r   = rem / 18;
            int q   = rem - r * 18;
            int row = y0 + r - 4;
            bool valid = (row >= 0) & (row < Hh) & (q >= 1) & (q <= 16);
            const float* src = f2b + (valid ? ((c0 + c) * HW + row * Ww + (q - 1) * 4) : 0);
            cp_async16(d2 + (uint32_t)(((c * SROWS + r) * SROW + q * 4) * 4), src, valid ? 16 : 0);
        }
        uint32_t d1 = s1_base + sel * (F1BUF * 4);
#pragma unroll
        for (int it = 0; it < 2; ++it) {
            int i = it * NTHR + tid;
            if (i < CHUNK * 32) {
                int c  = i >> 5;
                int rq = i & 31;
                cp_async16(d1 + (uint32_t)((c * 128 + rq * 4) * 4),
                           f1b + (c0 + c) * HW + rq * 4, 16);
            }
        }
        cp_commit();
    };

    float acc[NDX][4];
#pragma unroll
    for (int i = 0; i < NDX; ++i) { acc[i][0]=0.f; acc[i][1]=0.f; acc[i][2]=0.f; acc[i][3]=0.f; }

    stage(0, 0);

#pragma unroll 1
    for (int k = 0; k < NCH; ++k) {
        if (k + 1 < NCH) { stage((k + 1) * CHUNK, (k + 1) & 1); cp_wait<1>(); }
        else            { cp_wait<0>(); }
        __syncthreads();

        const float* sbuf = s_f2 + (k & 1) * F2BUF + (dy + ty) * SROW + x0 + VOFF;
        const float* abuf = s_f1 + (k & 1) * F1BUF + ty * Ww + x0;
#pragma unroll 8
        for (int c = 0; c < CHUNK; ++c) {
            float4 a = *(const float4*)(abuf + c * 128);
            const float* s = sbuf + c * (SROWS * SROW);
            float v[8];
            *(float4*)&v[0] = *(const float4*)(s);
            *(float4*)&v[4] = *(const float4*)(s + 4);
#pragma unroll
            for (int dx = 0; dx < NDX; ++dx) {
                const int j = DX0 + dx - VOFF;   // half0: dx, half1: dx+1
                acc[dx][0] += a.x * v[j + 0];
                acc[dx][1] += a.y * v[j + 1];
                acc[dx][2] += a.z * v[j + 2];
                acc[dx][3] += a.w * v[j + 3];
            }
        }
        __syncthreads();
    }

    // epilogue: scale by inv1 (this pixel) * inv2 (displaced pixel), relu, store
    float4 iv1 = *(const float4*)(&g_inv1[b][y * Ww + x0]);
    float e[8];
    *(float4*)&e[0] = *(const float4*)(&g_inv2p[b][y + dy][x0 + VOFF]);
    *(float4*)&e[4] = *(const float4*)(&g_inv2p[b][y + dy][x0 + VOFF + 4]);

    float* op = out + (size_t)(b * 81 + dy * PATCH + DX0) * HW + y * Ww + x0;
#pragma unroll
    for (int dx = 0; dx < NDX; ++dx) {
        const int j = DX0 + dx - VOFF;
        float4 o;
        o.x = fmaxf(acc[dx][0] * iv1.x * e[j + 0], 0.f);
        o.y = fmaxf(acc[dx][1] * iv1.y * e[j + 1], 0.f);
        o.z = fmaxf(acc[dx][2] * iv1.z * e[j + 2], 0.f);
        o.w = fmaxf(acc[dx][3] * iv1.w * e[j + 3], 0.f);
        *(float4*)(op + dx * HW) = o;
    }
}

__global__ __launch_bounds__(NTHR, 2)
void corr_kernel(const float* __restrict__ f1,
                 const float* __restrict__ f2,
                 float* __restrict__ out) {
    extern __shared__ float smem[];
    if (blockIdx.x & 1) corr_impl<5, 4>(smem, f1, f2, out);
    else                corr_impl<0, 5>(smem, f1, f2, out);
}

// ---------------------------------------------------------------------------
extern "C" void kernel_launch(void* const* d_in, const int* in_sizes, int n_in,
                              void* d_out, int out_size) {
    const float* f1 = (const float*)d_in[0];
    const float* f2 = (const float*)d_in[1];
    float* out = (float*)d_out;

    cudaFuncSetAttribute(corr_kernel,
                         cudaFuncAttributeMaxDynamicSharedMemorySize, SMEM_BYTES);

    invnorm_kernel<<<128, 256>>>(f1, f2);
    corr_kernel<<<Bz * (Hh / 2) * 2, NTHR, SMEM_BYTES>>>(f1, f2, out);
}

// round 6
// speedup vs baseline: 1.1942x; 1.1942x over previous
#include <cuda_runtime.h>
#include <cstdint>

#define Bz    4
#define Cc    64
#define Hh    64
#define Ww    64
#define HW    4096
#define CHW   (Cc*HW)
#define PATCH 9
#define CHUNK 16
#define NCH   (Cc/CHUNK)            // 4
#define TY    4                     // rows per CTA
#define F2ROWS (TY+8)               // 12
#define SROW  72
#define F2BUF (CHUNK*F2ROWS*SROW)   // 13824 floats
#define F1BUF (CHUNK*TY*Ww)         // 4096 floats
#define SMEM_FLOATS (2*(F2BUF+F1BUF))  // 35840
#define SMEM_BYTES  (SMEM_FLOATS*4)    // 143360
#define NTHR  576                   // 18 warps: dy(9) x row-pair(2)
#define NARRIVE 208                 // 192 f2-row copiers + 16 f1 copiers

typedef unsigned long long u64;

// scratch
__device__ float g_inv1[Bz][HW];
__device__ float g_inv2p[Bz][72][72];   // padded inverse norms of f2 (halo = 1.0)

__device__ __forceinline__ uint32_t smem_u32(const void* p) {
    uint32_t a;
    asm("{ .reg .u64 t; cvta.to.shared.u64 t, %1; cvt.u32.u64 %0, t; }" : "=r"(a) : "l"(p));
    return a;
}
__device__ __forceinline__ void bulk_g2s(uint32_t dst, const float* src, uint32_t bytes,
                                         uint32_t mbar) {
    asm volatile("cp.async.bulk.shared::cta.global.mbarrier::complete_tx::bytes "
                 "[%0], [%1], %2, [%3];"
                 :: "r"(dst), "l"(src), "r"(bytes), "r"(mbar) : "memory");
}
__device__ __forceinline__ void mbar_init(uint32_t mbar, uint32_t cnt) {
    asm volatile("mbarrier.init.shared.b64 [%0], %1;" :: "r"(mbar), "r"(cnt) : "memory");
}
__device__ __forceinline__ void mbar_arrive_tx(uint32_t mbar, uint32_t tx) {
    asm volatile("mbarrier.arrive.expect_tx.shared.b64 _, [%0], %1;"
                 :: "r"(mbar), "r"(tx) : "memory");
}
__device__ __forceinline__ void mbar_arrive(uint32_t mbar) {
    asm volatile("mbarrier.arrive.shared.b64 _, [%0];" :: "r"(mbar) : "memory");
}
__device__ __forceinline__ void mbar_wait(uint32_t mbar, uint32_t parity) {
    uint32_t done;
    asm volatile("{\n\t.reg .pred p;\n\t"
                 "mbarrier.try_wait.parity.acquire.cta.shared::cta.b64 p, [%1], %2;\n\t"
                 "selp.b32 %0, 1, 0, p;\n\t}"
                 : "=r"(done) : "r"(mbar), "r"(parity) : "memory");
    if (!done) {
        asm volatile("{\n\t.reg .pred P1;\n\t"
                     "WL_%=:\n\t"
                     "mbarrier.try_wait.parity.acquire.cta.shared::cta.b64 P1, [%0], %1, 0x989680;\n\t"
                     "@P1 bra.uni WD_%=;\n\t"
                     "bra.uni WL_%=;\n\t"
                     "WD_%=:\n\t}"
                     :: "r"(mbar), "r"(parity) : "memory");
    }
}
__device__ __forceinline__ u64 pk(float lo, float hi) {
    u64 r; asm("mov.b64 %0, {%1, %2};" : "=l"(r) : "f"(lo), "f"(hi)); return r;
}
__device__ __forceinline__ void fma2(u64& d, u64 a, u64 b) {
    asm("fma.rn.f32x2 %0, %1, %2, %0;" : "+l"(d) : "l"(a), "l"(b));
}
__device__ __forceinline__ void unpk(u64 p, float& lo, float& hi) {
    asm("mov.b64 {%0, %1}, %2;" : "=f"(lo), "=f"(hi) : "l"(p));
}

// ---------------------------------------------------------------------------
// Kernel 1: inverse L2 norms. 32768 threads, MLP=16, shfl-reduce. (proven)
// ---------------------------------------------------------------------------
__global__ void invnorm_kernel(const float* __restrict__ f1,
                               const float* __restrict__ f2) {
    int idx  = blockIdx.x * 256 + threadIdx.x;
    int cg   = idx & 3;
    int quad = (idx >> 2) & 1023;
    int b    = (idx >> 12) & 3;
    int feat = idx >> 14;
    const float* src = (feat ? f2 : f1) + b * CHW + quad * 4 + cg * 16 * HW;

    float4 s = make_float4(0.f, 0.f, 0.f, 0.f);
#pragma unroll
    for (int i = 0; i < 16; ++i) {
        float4 v = __ldg((const float4*)(src + i * HW));
        s.x += v.x * v.x; s.y += v.y * v.y; s.z += v.z * v.z; s.w += v.w * v.w;
    }
#pragma unroll
    for (int m = 1; m <= 2; m <<= 1) {
        s.x += __shfl_xor_sync(0xffffffffu, s.x, m);
        s.y += __shfl_xor_sync(0xffffffffu, s.y, m);
        s.z += __shfl_xor_sync(0xffffffffu, s.z, m);
        s.w += __shfl_xor_sync(0xffffffffu, s.w, m);
    }
    if (cg == 0) {
        float4 r;
        r.x = rsqrtf(s.x + 1e-6f); r.y = rsqrtf(s.y + 1e-6f);
        r.z = rsqrtf(s.z + 1e-6f); r.w = rsqrtf(s.w + 1e-6f);
        int y = quad >> 4, x = (quad & 15) << 2;
        if (feat == 0) *(float4*)&g_inv1[b][quad * 4] = r;
        else           *(float4*)&g_inv2p[b][y + 4][x + 4] = r;
    }
    if (idx < Bz * 72 * 72) {
        int bb = idx / 5184;
        int rc = idx - bb * 5184;
        int r  = rc / 72, cc = rc - r * 72;
        if (r < 4 || r >= 68 || cc < 4 || cc >= 68)
            g_inv2p[bb][r][cc] = 1.0f;
    }
}

// ---------------------------------------------------------------------------
// Kernel 2: correlation + relu.
//   grid = [b:4][yband:16][dxhalf:2] = 128 CTAs, 576 threads (18 warps).
//   warp = (dy, row-pair); lane = (row-in-pair, x-quad).
//   Staging: cp.async.bulk per (ch,row) -> mbarrier, double buffered.
//   Compute: packed fma.rn.f32x2.
// ---------------------------------------------------------------------------
template<int DX0, int NDX, int VOFF>
__device__ __forceinline__ void corr_impl(float* smem,
                                          const float* __restrict__ f1,
                                          const float* __restrict__ f2,
                                          float* __restrict__ out) {
    __shared__ u64 s_mbar[2];

    float* s_f2 = smem;
    float* s_f1 = smem + 2 * F2BUF;
    const uint32_t s2 = smem_u32(s_f2);
    const uint32_t s1 = smem_u32(s_f1);
    const uint32_t mb0 = smem_u32(&s_mbar[0]);
    const uint32_t mb1 = smem_u32(&s_mbar[1]);

    const int b    = blockIdx.x >> 5;
    const int y0   = ((blockIdx.x >> 1) & 15) * TY;
    const int tid  = threadIdx.x;
    const int w    = tid >> 5;
    const int lane = tid & 31;
    const int dy   = w >> 1;                    // 0..8
    const int ty   = ((w & 1) << 1) + (lane >> 4);  // 0..3
    const int x0   = (lane & 15) << 2;
    const int y    = y0 + ty;

    const float* f2b = f2 + b * CHW;
    const float* f1b = f1 + b * CHW;

    if (tid == 0) { mbar_init(mb0, NARRIVE); mbar_init(mb1, NARRIVE); }

    // zero halos (x halo cols always; interior of OOB rows) in both buffers
    for (int i = tid; i < 2 * CHUNK * F2ROWS * 2; i += NTHR) {  // buf,c,r,side
        int side = i & 1;
        int cr   = i >> 1;
        int buf  = cr >= CHUNK * F2ROWS;
        int cr2  = cr - buf * CHUNK * F2ROWS;
        int c    = cr2 / F2ROWS, r = cr2 - c * F2ROWS;
        float4 z = make_float4(0.f, 0.f, 0.f, 0.f);
        *(float4*)&s_f2[buf * F2BUF + (c * F2ROWS + r) * SROW + side * 68] = z;
    }
    for (int i = tid; i < 2 * CHUNK * F2ROWS; i += NTHR) {
        int buf = i >= CHUNK * F2ROWS;
        int cr  = i - buf * CHUNK * F2ROWS;
        int c   = cr / F2ROWS, r = cr - c * F2ROWS;
        int row = y0 + r - 4;
        if (row < 0 || row >= Hh) {
            float4 z = make_float4(0.f, 0.f, 0.f, 0.f);
#pragma unroll
            for (int q = 0; q < 16; ++q)
                *(float4*)&s_f2[buf * F2BUF + (c * F2ROWS + r) * SROW + 4 + q * 4] = z;
        }
    }
    __syncthreads();

    auto stage = [&](int c0, int sel) {
        uint32_t mb = sel ? mb1 : mb0;
        if (tid < CHUNK * F2ROWS) {                       // 192 f2-row copiers
            int c = tid / F2ROWS, r = tid - c * F2ROWS;
            int row = y0 + r - 4;
            if (row >= 0 && row < Hh) {
                mbar_arrive_tx(mb, 256);
                bulk_g2s(s2 + (uint32_t)((sel * F2BUF + (c * F2ROWS + r) * SROW + 4) * 4),
                         f2b + (c0 + c) * HW + row * Ww, 256, mb);
            } else {
                mbar_arrive(mb);
            }
        } else if (tid < NARRIVE) {                       // 16 f1 copiers (4 rows each)
            int c = tid - CHUNK * F2ROWS;
            mbar_arrive_tx(mb, TY * Ww * 4);
            bulk_g2s(s1 + (uint32_t)((sel * F1BUF + c * (TY * Ww)) * 4),
                     f1b + (c0 + c) * HW + y0 * Ww, TY * Ww * 4, mb);
        }
    };

    u64 acc2[NDX][2];
#pragma unroll
    for (int i = 0; i < NDX; ++i) { acc2[i][0] = 0ull; acc2[i][1] = 0ull; }

    stage(0, 0);
    stage(CHUNK, 1);

#pragma unroll 1
    for (int k = 0; k < NCH; ++k) {
        mbar_wait(k & 1 ? mb1 : mb0, (k >> 1) & 1);

        const float* sbuf = s_f2 + (k & 1) * F2BUF + (dy + ty) * SROW + x0 + VOFF;
        const float* abuf = s_f1 + (k & 1) * F1BUF + ty * Ww + x0;
#pragma unroll
        for (int c = 0; c < CHUNK; ++c) {
            ulonglong2 a2 = *(const ulonglong2*)(abuf + c * (TY * Ww)); // (a01,a23)
            const float* s = sbuf + c * (F2ROWS * SROW);
            float v[8];
            *(float4*)&v[0] = *(const float4*)(s);
            *(float4*)&v[4] = *(const float4*)(s + 4);
            u64 p[7];
#pragma unroll
            for (int kk = 0; kk < 7; ++kk) p[kk] = pk(v[kk], v[kk + 1]);
#pragma unroll
            for (int dxl = 0; dxl < NDX; ++dxl) {
                const int j = DX0 + dxl - VOFF;
                fma2(acc2[dxl][0], a2.x, p[j]);
                fma2(acc2[dxl][1], a2.y, p[j + 2]);
            }
        }
        if (k + 2 < NCH) {
            __syncthreads();
            stage((k + 2) * CHUNK, k & 1);
        }
    }

    // epilogue: inv1 (this pixel) * inv2 (displaced pixel), relu, store
    float4 iv1 = *(const float4*)(&g_inv1[b][y * Ww + x0]);
    float e[8];
    *(float4*)&e[0] = *(const float4*)(&g_inv2p[b][y + dy][x0 + VOFF]);
    *(float4*)&e[4] = *(const float4*)(&g_inv2p[b][y + dy][x0 + VOFF + 4]);

    float* op = out + (size_t)(b * 81 + dy * PATCH + DX0) * HW + y * Ww + x0;
#pragma unroll
    for (int dxl = 0; dxl < NDX; ++dxl) {
        const int j = DX0 + dxl - VOFF;
        float a0, a1, a2v, a3;
        unpk(acc2[dxl][0], a0, a1);
        unpk(acc2[dxl][1], a2v, a3);
        float4 o;
        o.x = fmaxf(a0  * iv1.x * e[j + 0], 0.f);
        o.y = fmaxf(a1  * iv1.y * e[j + 1], 0.f);
        o.z = fmaxf(a2v * iv1.z * e[j + 2], 0.f);
        o.w = fmaxf(a3  * iv1.w * e[j + 3], 0.f);
        *(float4*)(op + dxl * HW) = o;
    }
}

__global__ __launch_bounds__(NTHR, 1)
void corr_kernel(const float* __restrict__ f1,
                 const float* __restrict__ f2,
                 float* __restrict__ out) {
    extern __shared__ float smem[];
    if (blockIdx.x & 1) corr_impl<5, 4, 4>(smem, f1, f2, out);
    else                corr_impl<0, 5, 0>(smem, f1, f2, out);
}

// ---------------------------------------------------------------------------
extern "C" void kernel_launch(void* const* d_in, const int* in_sizes, int n_in,
                              void* d_out, int out_size) {
    const float* f1 = (const float*)d_in[0];
    const float* f2 = (const float*)d_in[1];
    float* out = (float*)d_out;

    cudaFuncSetAttribute(corr_kernel,
                         cudaFuncAttributeMaxDynamicSharedMemorySize, SMEM_BYTES);

    invnorm_kernel<<<128, 256>>>(f1, f2);
    corr_kernel<<<Bz * (Hh / TY) * 2, NTHR, SMEM_BYTES>>>(f1, f2, out);
}

// round 7
// speedup vs baseline: 1.2624x; 1.0570x over previous
#include <cuda_runtime.h>
#include <cstdint>

#define Bz    4
#define Cc    64
#define Hh    64
#define Ww    64
#define HW    4096
#define CHW   (Cc*HW)
#define PATCH 9
#define CHUNK 16
#define NCH   (Cc/CHUNK)            // 4
#define TY    2                     // rows per CTA
#define SROWS (TY+8)                // 10
#define SROW  72
#define F2BUF (CHUNK*SROWS*SROW)    // 11520 floats
#define F1BUF (CHUNK*TY*Ww)         // 2048 floats
#define SMEM_FLOATS (2*(F2BUF+F1BUF))  // 27136
#define SMEM_BYTES  (SMEM_FLOATS*4)    // 108544
#define NTHR  576                   // 18 warps: dy(9) x chalf(2)
#define NARRIVE (CHUNK*SROWS + CHUNK)  // 176
#define PSTRIDE 38                  // floats per partial-sum slot (2-way max conflict)

typedef unsigned long long u64;

// scratch
__device__ float g_inv1[Bz][HW];
__device__ float g_inv2p[Bz][72][72];   // padded inverse norms of f2 (halo = 1.0)

__device__ __forceinline__ uint32_t smem_u32(const void* p) {
    uint32_t a;
    asm("{ .reg .u64 t; cvta.to.shared.u64 t, %1; cvt.u32.u64 %0, t; }" : "=r"(a) : "l"(p));
    return a;
}
__device__ __forceinline__ void bulk_g2s(uint32_t dst, const float* src, uint32_t bytes,
                                         uint32_t mbar) {
    asm volatile("cp.async.bulk.shared::cta.global.mbarrier::complete_tx::bytes "
                 "[%0], [%1], %2, [%3];"
                 :: "r"(dst), "l"(src), "r"(bytes), "r"(mbar) : "memory");
}
__device__ __forceinline__ void mbar_init(uint32_t mbar, uint32_t cnt) {
    asm volatile("mbarrier.init.shared.b64 [%0], %1;" :: "r"(mbar), "r"(cnt) : "memory");
}
__device__ __forceinline__ void mbar_arrive_tx(uint32_t mbar, uint32_t tx) {
    asm volatile("mbarrier.arrive.expect_tx.shared.b64 _, [%0], %1;"
                 :: "r"(mbar), "r"(tx) : "memory");
}
__device__ __forceinline__ void mbar_arrive(uint32_t mbar) {
    asm volatile("mbarrier.arrive.shared.b64 _, [%0];" :: "r"(mbar) : "memory");
}
__device__ __forceinline__ void mbar_wait(uint32_t mbar, uint32_t parity) {
    uint32_t done;
    asm volatile("{\n\t.reg .pred p;\n\t"
                 "mbarrier.try_wait.parity.acquire.cta.shared::cta.b64 p, [%1], %2;\n\t"
                 "selp.b32 %0, 1, 0, p;\n\t}"
                 : "=r"(done) : "r"(mbar), "r"(parity) : "memory");
    if (!done) {
        asm volatile("{\n\t.reg .pred P1;\n\t"
                     "WL_%=:\n\t"
                     "mbarrier.try_wait.parity.acquire.cta.shared::cta.b64 P1, [%0], %1, 0x989680;\n\t"
                     "@P1 bra.uni WD_%=;\n\t"
                     "bra.uni WL_%=;\n\t"
                     "WD_%=:\n\t}"
                     :: "r"(mbar), "r"(parity) : "memory");
    }
}
__device__ __forceinline__ u64 pk(float lo, float hi) {
    u64 r; asm("mov.b64 %0, {%1, %2};" : "=l"(r) : "f"(lo), "f"(hi)); return r;
}
__device__ __forceinline__ void fma2(u64& d, u64 a, u64 b) {
    asm("fma.rn.f32x2 %0, %1, %2, %0;" : "+l"(d) : "l"(a), "l"(b));
}
__device__ __forceinline__ u64 add2(u64 a, u64 b) {
    u64 r; asm("add.rn.f32x2 %0, %1, %2;" : "=l"(r) : "l"(a), "l"(b)); return r;
}
__device__ __forceinline__ void unpk(u64 p, float& lo, float& hi) {
    asm("mov.b64 {%0, %1}, %2;" : "=f"(lo), "=f"(hi) : "l"(p));
}

// ---------------------------------------------------------------------------
// Kernel 1: inverse L2 norms. 32768 threads, MLP=16, shfl-reduce. (proven)
// ---------------------------------------------------------------------------
__global__ void invnorm_kernel(const float* __restrict__ f1,
                               const float* __restrict__ f2) {
    int idx  = blockIdx.x * 256 + threadIdx.x;
    int cg   = idx & 3;
    int quad = (idx >> 2) & 1023;
    int b    = (idx >> 12) & 3;
    int feat = idx >> 14;
    const float* src = (feat ? f2 : f1) + b * CHW + quad * 4 + cg * 16 * HW;

    float4 s = make_float4(0.f, 0.f, 0.f, 0.f);
#pragma unroll
    for (int i = 0; i < 16; ++i) {
        float4 v = __ldg((const float4*)(src + i * HW));
        s.x += v.x * v.x; s.y += v.y * v.y; s.z += v.z * v.z; s.w += v.w * v.w;
    }
#pragma unroll
    for (int m = 1; m <= 2; m <<= 1) {
        s.x += __shfl_xor_sync(0xffffffffu, s.x, m);
        s.y += __shfl_xor_sync(0xffffffffu, s.y, m);
        s.z += __shfl_xor_sync(0xffffffffu, s.z, m);
        s.w += __shfl_xor_sync(0xffffffffu, s.w, m);
    }
    if (cg == 0) {
        float4 r;
        r.x = rsqrtf(s.x + 1e-6f); r.y = rsqrtf(s.y + 1e-6f);
        r.z = rsqrtf(s.z + 1e-6f); r.w = rsqrtf(s.w + 1e-6f);
        int y = quad >> 4, x = (quad & 15) << 2;
        if (feat == 0) *(float4*)&g_inv1[b][quad * 4] = r;
        else           *(float4*)&g_inv2p[b][y + 4][x + 4] = r;
    }
    if (idx < Bz * 72 * 72) {
        int bb = idx / 5184;
        int rc = idx - bb * 5184;
        int r  = rc / 72, cc = rc - r * 72;
        if (r < 4 || r >= 68 || cc < 4 || cc >= 68)
            g_inv2p[bb][r][cc] = 1.0f;
    }
}

// ---------------------------------------------------------------------------
// Kernel 2: correlation + relu, channel-split.
//   grid = [b:4][ypair:32] = 128 CTAs, 576 threads = 18 warps:
//   warp = (dy 0..8, chalf 0..1); lane = (ty 0..1, xq 0..15) -> 4 px.
//   Each thread: 4 px, its dy, ALL 9 dx, channels c%2==chalf of every chunk.
//   Halves combined in-CTA via smem; epilogue by chalf 0.
// ---------------------------------------------------------------------------
__global__ __launch_bounds__(NTHR, 1)
void corr_kernel(const float* __restrict__ f1,
                 const float* __restrict__ f2,
                 float* __restrict__ out) {
    extern __shared__ float smem[];
    __shared__ u64 s_mbar[2];

    float* s_f2 = smem;
    float* s_f1 = smem + 2 * F2BUF;
    const uint32_t s2 = smem_u32(s_f2);
    const uint32_t s1 = smem_u32(s_f1);
    const uint32_t mb0 = smem_u32(&s_mbar[0]);
    const uint32_t mb1 = smem_u32(&s_mbar[1]);

    const int b    = blockIdx.x >> 5;
    const int y0   = (blockIdx.x & 31) * TY;
    const int tid  = threadIdx.x;
    const int w    = tid >> 5;
    const int lane = tid & 31;
    const int dy   = w >> 1;                // 0..8
    const int ch   = w & 1;                 // channel parity
    const int ty   = lane >> 4;             // 0..1
    const int x0   = (lane & 15) << 2;
    const int y    = y0 + ty;

    const float* f2b = f2 + b * CHW;
    const float* f1b = f1 + b * CHW;

    if (tid == 0) { mbar_init(mb0, NARRIVE); mbar_init(mb1, NARRIVE); }

    // zero halos (x halo cols; interiors of OOB rows) in both buffers
    for (int i = tid; i < 2 * CHUNK * SROWS * 2; i += NTHR) {
        int side = i & 1;
        int cr   = i >> 1;
        int buf  = cr >= CHUNK * SROWS;
        int cr2  = cr - buf * CHUNK * SROWS;
        int c    = cr2 / SROWS, r = cr2 - c * SROWS;
        float4 z = make_float4(0.f, 0.f, 0.f, 0.f);
        *(float4*)&s_f2[buf * F2BUF + (c * SROWS + r) * SROW + side * 68] = z;
    }
    for (int i = tid; i < 2 * CHUNK * SROWS; i += NTHR) {
        int buf = i >= CHUNK * SROWS;
        int cr  = i - buf * CHUNK * SROWS;
        int c   = cr / SROWS, r = cr - c * SROWS;
        int row = y0 + r - 4;
        if (row < 0 || row >= Hh) {
            float4 z = make_float4(0.f, 0.f, 0.f, 0.f);
#pragma unroll
            for (int q = 0; q < 16; ++q)
                *(float4*)&s_f2[buf * F2BUF + (c * SROWS + r) * SROW + 4 + q * 4] = z;
        }
    }
    __syncthreads();

    auto stage = [&](int c0, int sel) {
        uint32_t mb = sel ? mb1 : mb0;
        if (tid < CHUNK * SROWS) {                   // 160 f2-row copiers
            int c = tid / SROWS, r = tid - c * SROWS;
            int row = y0 + r - 4;
            if (row >= 0 && row < Hh) {
                mbar_arrive_tx(mb, 256);
                bulk_g2s(s2 + (uint32_t)((sel * F2BUF + (c * SROWS + r) * SROW + 4) * 4),
                         f2b + (c0 + c) * HW + row * Ww, 256, mb);
            } else {
                mbar_arrive(mb);
            }
        } else if (tid < NARRIVE) {                  // 16 f1 copiers (TY rows each)
            int c = tid - CHUNK * SROWS;
            mbar_arrive_tx(mb, TY * Ww * 4);
            bulk_g2s(s1 + (uint32_t)((sel * F1BUF + c * (TY * Ww)) * 4),
                     f1b + (c0 + c) * HW + y0 * Ww, TY * Ww * 4, mb);
        }
    };

    u64 acc2[PATCH][2];
#pragma unroll
    for (int i = 0; i < PATCH; ++i) { acc2[i][0] = 0ull; acc2[i][1] = 0ull; }

    stage(0, 0);
    stage(CHUNK, 1);

#pragma unroll 1
    for (int k = 0; k < NCH; ++k) {
        mbar_wait(k & 1 ? mb1 : mb0, (k >> 1) & 1);

        const float* sbuf = s_f2 + (k & 1) * F2BUF + (dy + ty) * SROW + x0;
        const float* abuf = s_f1 + (k & 1) * F1BUF + ty * Ww + x0;
#pragma unroll
        for (int i = 0; i < CHUNK / 2; ++i) {
            const int c = (i << 1) + ch;             // this half's channels
            ulonglong2 a2 = *(const ulonglong2*)(abuf + c * (TY * Ww)); // (a01,a23)
            const float* s = sbuf + c * (SROWS * SROW);
            float v[12];
            *(float4*)&v[0] = *(const float4*)(s);
            *(float4*)&v[4] = *(const float4*)(s + 4);
            *(float4*)&v[8] = *(const float4*)(s + 8);
            u64 p[11];
#pragma unroll
            for (int j = 0; j < 11; ++j) p[j] = pk(v[j], v[j + 1]);
#pragma unroll
            for (int d = 0; d < PATCH; ++d) {
                fma2(acc2[d][0], a2.x, p[d]);
                fma2(acc2[d][1], a2.y, p[d + 2]);
            }
        }
        if (k + 2 < NCH) {
            __syncthreads();
            stage((k + 2) * CHUNK, k & 1);
        }
    }

    // ---- combine channel halves in-CTA (chalf1 -> smem -> chalf0)
    __syncthreads();                       // everyone done with smem buffers
    const int pid = dy * 32 + lane;        // 0..287
    u64* slot = (u64*)(smem + pid * PSTRIDE);
    if (ch) {
#pragma unroll
        for (int d = 0; d < PATCH; ++d) {
            slot[d * 2 + 0] = acc2[d][0];
            slot[d * 2 + 1] = acc2[d][1];
        }
    }
    __syncthreads();
    if (!ch) {
        // epilogue: inv1 (this pixel) * inv2 (displaced pixel), relu, store
        float4 iv1 = *(const float4*)(&g_inv1[b][y * Ww + x0]);
        float e[12];
        *(float4*)&e[0] = *(const float4*)(&g_inv2p[b][y + dy][x0]);
        *(float4*)&e[4] = *(const float4*)(&g_inv2p[b][y + dy][x0 + 4]);
        *(float4*)&e[8] = *(const float4*)(&g_inv2p[b][y + dy][x0 + 8]);

        float* op = out + (size_t)(b * 81 + dy * PATCH) * HW + y * Ww + x0;
#pragma unroll
        for (int d = 0; d < PATCH; ++d) {
            u64 t0 = add2(acc2[d][0], slot[d * 2 + 0]);
            u64 t1 = add2(acc2[d][1], slot[d * 2 + 1]);
            float a0, a1, a2v, a3;
            unpk(t0, a0, a1);
            unpk(t1, a2v, a3);
            float4 o;
            o.x = fmaxf(a0  * iv1.x * e[d + 0], 0.f);
            o.y = fmaxf(a1  * iv1.y * e[d + 1], 0.f);
            o.z = fmaxf(a2v * iv1.z * e[d + 2], 0.f);
            o.w = fmaxf(a3  * iv1.w * e[d + 3], 0.f);
            *(float4*)(op + d * HW) = o;
        }
    }
}

// ---------------------------------------------------------------------------
extern "C" void kernel_launch(void* const* d_in, const int* in_sizes, int n_in,
                              void* d_out, int out_size) {
    const float* f1 = (const float*)d_in[0];
    const float* f2 = (const float*)d_in[1];
    float* out = (float*)d_out;

    cudaFuncSetAttribute(corr_kernel,
                         cudaFuncAttributeMaxDynamicSharedMemorySize, SMEM_BYTES);

    invnorm_kernel<<<128, 256>>>(f1, f2);
    corr_kernel<<<Bz * (Hh / TY), NTHR, SMEM_BYTES>>>(f1, f2, out);
}